// round 14
// baseline (speedup 1.0000x reference)
#include <cuda_runtime.h>
#include <cstdint>

// Problem constants (static in the reference)
#define N_NODES 100000
#define C_CH    32
#define NC      (N_NODES * C_CH)
#define CAP     64          // bucket capacity; deg ~ Poisson(16), P(deg>=64) ~ 1e-19
#define CHUNK   16          // edges per pipeline chunk (4 cp.async warp-ops)
#define WPB     8           // warps (nodes) per block

// Scratch (alloc-free rule: __device__ globals; zero-initialized at module load)
__device__ int   g_cnt[N_NODES];
__device__ int   g_bucket[(size_t)N_NODES * CAP];
__device__ float g_t1[NC];

// ---------------------------------------------------------------------------
// Bin edges by destination (at its scattered-op/LSU structural floor; R4/R5).
// Requires g_cnt == 0 on entry (initial zero-init; re-zeroed by gather<1>).
// ---------------------------------------------------------------------------
__global__ void bin_kernel(const int* __restrict__ esrc,
                           const int* __restrict__ edst,
                           int E) {
    int e = blockIdx.x * blockDim.x + threadIdx.x;
    if (e >= E) return;
    int d = __ldg(edst + e);
    int s = __ldg(esrc + e);
    int pos = atomicAdd(&g_cnt[d], 1);
    if (pos < CAP) g_bucket[(size_t)d * CAP + pos] = s;
}

__device__ __forceinline__ void cp_async16(float4* smem_dst, const float4* gsrc,
                                           int src_bytes) {
    uint32_t d = (uint32_t)__cvta_generic_to_shared(smem_dst);
    asm volatile("cp.async.cg.shared.global [%0], [%1], 16, %2;\n"
                 :: "r"(d), "l"(gsrc), "r"(src_bytes));
}

// ---------------------------------------------------------------------------
// Gather pass: one warp per node; edges in CHUNK=16 batches staged to smem
// via cp.async.cg (L1-BYPASS: R13 post-mortem says passes are L1-miss
// concurrency bound; .cg goes L2->smem with no MSHR / register-MLP cap).
// Double-buffered: chunk c+1 issues while chunk c is reduced.
// Lane (grp=lane>>3, sub=lane&7) copies+reduces slot sub of edges = grp mod 4;
// each lane reads only smem it wrote -> no syncwarp inside the loop.
// Tail edges use src-size 0 (hardware zero-fill).
//   PASS 0: t1 = deg*x - agg ; y = w0*x + w1*t1
//   PASS 1: y += w2*(deg*t1 - agg) ; re-zero cnt
// ---------------------------------------------------------------------------
template <int PASS>
__global__ void __launch_bounds__(WPB * 32)
gather_kernel(const float* __restrict__ x,
              const float* __restrict__ w,
              float* __restrict__ y) {
    __shared__ float4 buf[WPB][2][CHUNK][8];   // 32 KB/block

    int wid  = threadIdx.x >> 5;
    int lane = threadIdx.x & 31;
    int node = blockIdx.x * WPB + wid;
    if (node >= N_NODES) return;

    int grp = lane >> 3;   // edge slot within a 4-edge warp-op
    int sub = lane & 7;    // float4 slot within the 32-ch row

    int deg = g_cnt[node];
    const int* __restrict__ bkt = g_bucket + (size_t)node * CAP;
    const float* __restrict__ rows = (PASS == 0) ? x : (const float*)g_t1;

    int nchunks = (deg + CHUNK - 1) / CHUNK;

    // issue one chunk: 4 cp.async warp-ops (16 edges)
    auto issue = [&](int c, int pb) {
        int ebase = c * CHUNK;
        #pragma unroll
        for (int k = 0; k < 4; k++) {
            int e = ebase + k * 4 + grp;
            int valid = (e < deg);
            int s = valid ? __ldg(bkt + e) : 0;
            const float4* src = reinterpret_cast<const float4*>(rows + (size_t)s * C_CH) + sub;
            cp_async16(&buf[wid][pb][k * 4 + grp][sub], src, valid ? 16 : 0);
        }
        asm volatile("cp.async.commit_group;\n" ::);
    };

    float4 a = make_float4(0.f, 0.f, 0.f, 0.f);
    if (nchunks > 0) {
        issue(0, 0);
        int pb = 0;
        for (int c = 0; c < nchunks; c++) {
            bool more = (c + 1 < nchunks);
            if (more) {
                issue(c + 1, pb ^ 1);
                asm volatile("cp.async.wait_group 1;\n" ::);
            } else {
                asm volatile("cp.async.wait_group 0;\n" ::);
            }
            #pragma unroll
            for (int k = 0; k < 4; k++) {
                float4 v = buf[wid][pb][k * 4 + grp][sub];
                a.x += v.x; a.y += v.y; a.z += v.z; a.w += v.w;
            }
            pb ^= 1;
        }
    }

    // fold the 4 group partials (groups differ in lane bits 3..4)
    #pragma unroll
    for (int off = 8; off <= 16; off <<= 1) {
        a.x += __shfl_xor_sync(0xffffffffu, a.x, off);
        a.y += __shfl_xor_sync(0xffffffffu, a.y, off);
        a.z += __shfl_xor_sync(0xffffffffu, a.z, off);
        a.w += __shfl_xor_sync(0xffffffffu, a.w, off);
    }

    // lanes 0-7 hold the full row aggregate; float4 epilogue there
    if (grp == 0) {
        float dg = (float)deg;
        const float4* x4p = reinterpret_cast<const float4*>(x    + (size_t)node * C_CH) + sub;
        float4*       t4p = reinterpret_cast<float4*>      (g_t1 + (size_t)node * C_CH) + sub;
        float4*       y4p = reinterpret_cast<float4*>      (y    + (size_t)node * C_CH) + sub;

        if (PASS == 0) {
            float w0 = __ldg(w + 0);
            float w1 = __ldg(w + 1);
            float4 xv = __ldg(x4p);
            float4 t;
            t.x = dg * xv.x - a.x;
            t.y = dg * xv.y - a.y;
            t.z = dg * xv.z - a.z;
            t.w = dg * xv.w - a.w;
            *t4p = t;
            float4 out;
            out.x = w0 * xv.x + w1 * t.x;
            out.y = w0 * xv.y + w1 * t.y;
            out.z = w0 * xv.z + w1 * t.z;
            out.w = w0 * xv.w + w1 * t.w;
            *y4p = out;
        } else {
            float w2 = __ldg(w + 2);
            float4 tv = *t4p;
            float4 yv = *y4p;
            yv.x += w2 * (dg * tv.x - a.x);
            yv.y += w2 * (dg * tv.y - a.y);
            yv.z += w2 * (dg * tv.z - a.z);
            yv.w += w2 * (dg * tv.w - a.w);
            *y4p = yv;
            if (lane == 0) g_cnt[node] = 0;   // restore invariant
        }
    }
}

// ---------------------------------------------------------------------------
extern "C" void kernel_launch(void* const* d_in, const int* in_sizes, int n_in,
                              void* d_out, int out_size) {
    const float* x    = (const float*)d_in[0];
    const float* w    = (const float*)d_in[1];
    const int*   esrc = (const int*)d_in[2];
    const int*   edst = (const int*)d_in[3];
    float*       y    = (float*)d_out;
    int E = in_sizes[2];

    const int TPB = 256;
    int bin_blocks    = (E + TPB - 1) / TPB;                 // 6250
    int gather_blocks = (N_NODES + WPB - 1) / WPB;           // 12500

    bin_kernel<<<bin_blocks, TPB>>>(esrc, edst, E);
    gather_kernel<0><<<gather_blocks, WPB * 32>>>(x, w, y);
    gather_kernel<1><<<gather_blocks, WPB * 32>>>(x, w, y);
}